// round 1
// baseline (speedup 1.0000x reference)
#include <cuda_runtime.h>
#include <math.h>

// Window attention: B=8, C=512, H=W=128, heads=8, ws=8, hd=64.
// One CTA per window (b, head, wy, wx): 64 tokens x 64 dims.
// Grid = 8*8*16*16 = 16384 CTAs, 256 threads each.

#define HD    64
#define NT    64
#define PSTR  68           // padded smem row stride (floats), 16B-aligned rows
#define TILE_FLOATS (64 * PSTR)

__global__ __launch_bounds__(256, 3)
void win_attn_kernel(const float* __restrict__ q,
                     const float* __restrict__ k,
                     const float* __restrict__ v,
                     float* __restrict__ out)
{
    extern __shared__ float smem[];
    float* qs = smem;                   // [d][tok]  (d-major)
    float* ks = smem + TILE_FLOATS;     // [d][tok]
    float* vs = smem + 2 * TILE_FLOATS; // [tok][d]  (token-major)
    float* ps = smem + 3 * TILE_FLOATS; // [i][j]    scores / probs

    const int tid = threadIdx.x;
    const int win = blockIdx.x;
    const int wx  = win & 15;
    const int wy  = (win >> 4) & 15;
    const int bh  = win >> 8;           // b*8 + head

    const size_t base = (size_t)bh * (64 * 16384) + (size_t)(wy * 8) * 128 + (size_t)(wx * 8);

    // ---- Load Q, K, V tiles (coalesced float4 over x) ----
    #pragma unroll
    for (int c = 0; c < 4; c++) {
        int lin = c * 256 + tid;        // 1024 float4 chunks: (d, y, x4)
        int x4  = (lin & 1) * 4;
        int y   = (lin >> 1) & 7;
        int d   = lin >> 4;
        size_t g = base + (size_t)d * 16384 + (size_t)y * 128 + x4;
        float4 qv = *(const float4*)(q + g);
        float4 kv = *(const float4*)(k + g);
        float4 vv = *(const float4*)(v + g);
        int t = y * 8 + x4;
        *(float4*)&qs[d * PSTR + t] = qv;
        *(float4*)&ks[d * PSTR + t] = kv;
        vs[(t + 0) * PSTR + d] = vv.x;
        vs[(t + 1) * PSTR + d] = vv.y;
        vs[(t + 2) * PSTR + d] = vv.z;
        vs[(t + 3) * PSTR + d] = vv.w;
    }
    __syncthreads();

    // ---- S = Q K^T * scale : 16x16 threads, 4x4 tile each ----
    const int tx = tid & 15;
    const int ty = tid >> 4;
    const int i0 = ty * 4;
    const int j0 = tx * 4;

    float acc[4][4];
    #pragma unroll
    for (int a = 0; a < 4; a++)
        #pragma unroll
        for (int b = 0; b < 4; b++) acc[a][b] = 0.f;

    #pragma unroll 8
    for (int d = 0; d < HD; d++) {
        float4 qv = *(const float4*)&qs[d * PSTR + i0];   // broadcast within warp
        float4 kv = *(const float4*)&ks[d * PSTR + j0];
        float qr[4] = {qv.x, qv.y, qv.z, qv.w};
        float kr[4] = {kv.x, kv.y, kv.z, kv.w};
        #pragma unroll
        for (int a = 0; a < 4; a++)
            #pragma unroll
            for (int b = 0; b < 4; b++)
                acc[a][b] = fmaf(qr[a], kr[b], acc[a][b]);
    }

    const float scale = 0.125f;  // hd^-0.5 = 1/8
    #pragma unroll
    for (int a = 0; a < 4; a++) {
        float4 sv = make_float4(acc[a][0] * scale, acc[a][1] * scale,
                                acc[a][2] * scale, acc[a][3] * scale);
        *(float4*)&ps[(i0 + a) * PSTR + j0] = sv;
    }
    __syncthreads();

    // ---- Softmax over each row (64 rows, 4 lanes per row) ----
    {
        int row = tid >> 2;
        int jc  = (tid & 3) * 16;
        float* prow = &ps[row * PSTR + jc];
        float pr[16];
        #pragma unroll
        for (int s = 0; s < 16; s++) pr[s] = prow[s];

        float m = pr[0];
        #pragma unroll
        for (int s = 1; s < 16; s++) m = fmaxf(m, pr[s]);
        m = fmaxf(m, __shfl_xor_sync(0xffffffffu, m, 1));
        m = fmaxf(m, __shfl_xor_sync(0xffffffffu, m, 2));

        float sum = 0.f;
        #pragma unroll
        for (int s = 0; s < 16; s++) { pr[s] = __expf(pr[s] - m); sum += pr[s]; }
        sum += __shfl_xor_sync(0xffffffffu, sum, 1);
        sum += __shfl_xor_sync(0xffffffffu, sum, 2);
        float inv = __fdividef(1.f, sum);

        #pragma unroll
        for (int s = 0; s < 16; s++) prow[s] = pr[s] * inv;
    }
    __syncthreads();

    // ---- O = P V : thread (ty,tx) -> O[i0..i0+3][d0..d0+3] ----
    const int d0 = tx * 4;
    float o[4][4];
    #pragma unroll
    for (int a = 0; a < 4; a++)
        #pragma unroll
        for (int b = 0; b < 4; b++) o[a][b] = 0.f;

    #pragma unroll 4
    for (int j = 0; j < NT; j++) {
        float4 vv = *(const float4*)&vs[j * PSTR + d0];
        float vr[4] = {vv.x, vv.y, vv.z, vv.w};
        float p0 = ps[(i0 + 0) * PSTR + j];   // 2-address broadcast within warp
        float p1 = ps[(i0 + 1) * PSTR + j];
        float p2 = ps[(i0 + 2) * PSTR + j];
        float p3 = ps[(i0 + 3) * PSTR + j];
        #pragma unroll
        for (int b = 0; b < 4; b++) {
            o[0][b] = fmaf(p0, vr[b], o[0][b]);
            o[1][b] = fmaf(p1, vr[b], o[1][b]);
            o[2][b] = fmaf(p2, vr[b], o[2][b]);
            o[3][b] = fmaf(p3, vr[b], o[3][b]);
        }
    }

    // ---- Stage O into qs ([d][tok]) for coalesced global store ----
    // qs is dead after the S phase (post-sync), safe to overwrite.
    #pragma unroll
    for (int b = 0; b < 4; b++) {
        float4 ov = make_float4(o[0][b], o[1][b], o[2][b], o[3][b]);
        *(float4*)&qs[(d0 + b) * PSTR + i0] = ov;
    }
    __syncthreads();

    #pragma unroll
    for (int c = 0; c < 4; c++) {
        int lin = c * 256 + tid;
        int x4  = (lin & 1) * 4;
        int y   = (lin >> 1) & 7;
        int d   = lin >> 4;
        int t = y * 8 + x4;
        float4 ov = *(const float4*)&qs[d * PSTR + t];
        *(float4*)(out + base + (size_t)d * 16384 + (size_t)y * 128 + x4) = ov;
    }
}

extern "C" void kernel_launch(void* const* d_in, const int* in_sizes, int n_in,
                              void* d_out, int out_size)
{
    const float* q = (const float*)d_in[0];
    const float* k = (const float*)d_in[1];
    const float* v = (const float*)d_in[2];
    float* out = (float*)d_out;

    const int smem_bytes = 4 * TILE_FLOATS * sizeof(float);  // 69632
    cudaFuncSetAttribute(win_attn_kernel,
                         cudaFuncAttributeMaxDynamicSharedMemorySize, smem_bytes);

    dim3 grid(16384);
    dim3 block(256);
    win_attn_kernel<<<grid, block, smem_bytes>>>(q, k, v, out);
}

// round 2
// speedup vs baseline: 1.0420x; 1.0420x over previous
#include <cuda_runtime.h>
#include <math.h>

// Window attention: B=8, C=512, H=W=128, heads=8, ws=8, hd=64.
// One CTA per window (b, head, wy, wx): 64 tokens x 64 dims.
// Grid = 8*8*16*16 = 16384 CTAs, 256 threads each.

#define HD    64
#define NT    64
#define PSTR  68           // padded smem row stride (floats), 16B-aligned rows
#define TILE_FLOATS (64 * PSTR)

__global__ __launch_bounds__(256, 3)
void win_attn_kernel(const float* __restrict__ q,
                     const float* __restrict__ k,
                     const float* __restrict__ v,
                     float* __restrict__ out)
{
    extern __shared__ float smem[];
    float* qs = smem;                   // [d][tok]  (d-major)
    float* ks = smem + TILE_FLOATS;     // [d][tok]
    float* vs = smem + 2 * TILE_FLOATS; // [tok][d]  (token-major)
    float* ps = smem + 3 * TILE_FLOATS; // [i][j]    scores / probs

    const int tid = threadIdx.x;
    const int win = blockIdx.x;
    const int wx  = win & 15;
    const int wy  = (win >> 4) & 15;
    const int bh  = win >> 8;           // b*8 + head

    const size_t base = (size_t)bh * (64 * 16384) + (size_t)(wy * 8) * 128 + (size_t)(wx * 8);

    // ---- Load Q, K, V tiles (coalesced float4 over x) ----
    #pragma unroll
    for (int c = 0; c < 4; c++) {
        int lin = c * 256 + tid;        // 1024 float4 chunks: (d, y, x4)
        int x4  = (lin & 1) * 4;
        int y   = (lin >> 1) & 7;
        int d   = lin >> 4;
        size_t g = base + (size_t)d * 16384 + (size_t)y * 128 + x4;
        float4 qv = *(const float4*)(q + g);
        float4 kv = *(const float4*)(k + g);
        float4 vv = *(const float4*)(v + g);
        int t = y * 8 + x4;
        *(float4*)&qs[d * PSTR + t] = qv;
        *(float4*)&ks[d * PSTR + t] = kv;
        vs[(t + 0) * PSTR + d] = vv.x;
        vs[(t + 1) * PSTR + d] = vv.y;
        vs[(t + 2) * PSTR + d] = vv.z;
        vs[(t + 3) * PSTR + d] = vv.w;
    }
    __syncthreads();

    // ---- S = Q K^T * scale : 16x16 threads, 4x4 tile each ----
    const int tx = tid & 15;
    const int ty = tid >> 4;
    const int i0 = ty * 4;
    const int j0 = tx * 4;

    float acc[4][4];
    #pragma unroll
    for (int a = 0; a < 4; a++)
        #pragma unroll
        for (int b = 0; b < 4; b++) acc[a][b] = 0.f;

    #pragma unroll 8
    for (int d = 0; d < HD; d++) {
        float4 qv = *(const float4*)&qs[d * PSTR + i0];   // broadcast within warp
        float4 kv = *(const float4*)&ks[d * PSTR + j0];
        float qr[4] = {qv.x, qv.y, qv.z, qv.w};
        float kr[4] = {kv.x, kv.y, kv.z, kv.w};
        #pragma unroll
        for (int a = 0; a < 4; a++)
            #pragma unroll
            for (int b = 0; b < 4; b++)
                acc[a][b] = fmaf(qr[a], kr[b], acc[a][b]);
    }

    const float scale = 0.125f;  // hd^-0.5 = 1/8
    #pragma unroll
    for (int a = 0; a < 4; a++) {
        float4 sv = make_float4(acc[a][0] * scale, acc[a][1] * scale,
                                acc[a][2] * scale, acc[a][3] * scale);
        *(float4*)&ps[(i0 + a) * PSTR + j0] = sv;
    }
    __syncthreads();

    // ---- Softmax over each row (64 rows, 4 lanes per row) ----
    {
        int row = tid >> 2;
        int jc  = (tid & 3) * 16;
        float* prow = &ps[row * PSTR + jc];
        float pr[16];
        #pragma unroll
        for (int s = 0; s < 16; s++) pr[s] = prow[s];

        float m = pr[0];
        #pragma unroll
        for (int s = 1; s < 16; s++) m = fmaxf(m, pr[s]);
        m = fmaxf(m, __shfl_xor_sync(0xffffffffu, m, 1));
        m = fmaxf(m, __shfl_xor_sync(0xffffffffu, m, 2));

        float sum = 0.f;
        #pragma unroll
        for (int s = 0; s < 16; s++) { pr[s] = __expf(pr[s] - m); sum += pr[s]; }
        sum += __shfl_xor_sync(0xffffffffu, sum, 1);
        sum += __shfl_xor_sync(0xffffffffu, sum, 2);
        float inv = __fdividef(1.f, sum);

        #pragma unroll
        for (int s = 0; s < 16; s++) prow[s] = pr[s] * inv;
    }
    __syncthreads();

    // ---- O = P V : thread (ty,tx) -> O[i0..i0+3][d0..d0+3] ----
    const int d0 = tx * 4;
    float o[4][4];
    #pragma unroll
    for (int a = 0; a < 4; a++)
        #pragma unroll
        for (int b = 0; b < 4; b++) o[a][b] = 0.f;

    #pragma unroll 4
    for (int j = 0; j < NT; j++) {
        float4 vv = *(const float4*)&vs[j * PSTR + d0];
        float vr[4] = {vv.x, vv.y, vv.z, vv.w};
        float p0 = ps[(i0 + 0) * PSTR + j];   // 2-address broadcast within warp
        float p1 = ps[(i0 + 1) * PSTR + j];
        float p2 = ps[(i0 + 2) * PSTR + j];
        float p3 = ps[(i0 + 3) * PSTR + j];
        #pragma unroll
        for (int b = 0; b < 4; b++) {
            o[0][b] = fmaf(p0, vr[b], o[0][b]);
            o[1][b] = fmaf(p1, vr[b], o[1][b]);
            o[2][b] = fmaf(p2, vr[b], o[2][b]);
            o[3][b] = fmaf(p3, vr[b], o[3][b]);
        }
    }

    // ---- Stage O into qs ([d][tok]) for coalesced global store ----
    // qs is dead after the S phase (post-sync), safe to overwrite.
    #pragma unroll
    for (int b = 0; b < 4; b++) {
        float4 ov = make_float4(o[0][b], o[1][b], o[2][b], o[3][b]);
        *(float4*)&qs[(d0 + b) * PSTR + i0] = ov;
    }
    __syncthreads();

    #pragma unroll
    for (int c = 0; c < 4; c++) {
        int lin = c * 256 + tid;
        int x4  = (lin & 1) * 4;
        int y   = (lin >> 1) & 7;
        int d   = lin >> 4;
        int t = y * 8 + x4;
        float4 ov = *(const float4*)&qs[d * PSTR + t];
        *(float4*)(out + base + (size_t)d * 16384 + (size_t)y * 128 + x4) = ov;
    }
}

extern "C" void kernel_launch(void* const* d_in, const int* in_sizes, int n_in,
                              void* d_out, int out_size)
{
    const float* q = (const float*)d_in[0];
    const float* k = (const float*)d_in[1];
    const float* v = (const float*)d_in[2];
    float* out = (float*)d_out;

    const int smem_bytes = 4 * TILE_FLOATS * sizeof(float);  // 69632
    cudaFuncSetAttribute(win_attn_kernel,
                         cudaFuncAttributeMaxDynamicSharedMemorySize, smem_bytes);

    dim3 grid(16384);
    dim3 block(256);
    win_attn_kernel<<<grid, block, smem_bytes>>>(q, k, v, out);
}